// round 11
// baseline (speedup 1.0000x reference)
#include <cuda_runtime.h>

typedef unsigned long long u64;

#define H_      51
#define TSTEPS  512
#define BTOT    1024
#define NB      8
#define NBLK    (BTOT / NB)        // 128
#define NTHR    768
#define GP      224                // padded gate slots, permuted s = 4u+q
#define HROW    108                // per-batch h row: h1[0:51], pad, h2[52:103], pad
#define HC      27                 // ulonglong2 chunks per h row
#define LVL     (NB * GP)          // 1792 floats per partial level

// ---- shared memory layout (float offsets) ----
#define OFF_W1   0                          // [13][224][4]
#define OFF_W2   (OFF_W1 + 13*GP*4)         // [26][224][4]
#define OFF_XS   (OFF_W2 + 26*GP*4)         // [512][8]
#define OFF_HS   (OFF_XS + TSTEPS*8)        // [8][108]
#define OFF_C1   (OFF_HS + NB*HROW)         // [8][52]
#define OFF_C2   (OFF_C1 + NB*52)           // [8][52]
#define OFF_PB1  (OFF_C2 + NB*52)           // 2 levels x [8][224]
#define OFF_PB2  (OFF_PB1 + 2*LVL)          // 4 levels x [8][224]
#define OFF_B1   (OFF_PB2 + 4*LVL)          // 224
#define OFF_B2   (OFF_B1 + GP)              // 224
#define OFF_WI1  (OFF_B2 + GP)              // 224
#define OFF_WL   (OFF_WI1 + GP)             // 56
#define OFF_BL   (OFF_WL + 56)              // 4
#define SMEM_FLOATS (OFF_BL + 4)
#define SMEM_BYTES  (SMEM_FLOATS * 4)       // ~209 KB

__device__ __forceinline__ void ffma2(u64 &d, u64 a, u64 b) {
    asm("fma.rn.f32x2 %0, %1, %2, %0;" : "+l"(d) : "l"(a), "l"(b));
}
__device__ __forceinline__ float2 unpk(u64 v) {
    float2 r;
    asm("mov.b64 {%0, %1}, %2;" : "=f"(r.x), "=f"(r.y) : "l"(v));
    return r;
}
__device__ __forceinline__ float sigf(float x) {
    return __fdividef(1.0f, 1.0f + __expf(-x));
}
__device__ __forceinline__ float tanhfast(float x) {
    return __fdividef(2.0f, 1.0f + __expf(-2.0f * x)) - 1.0f;
}

// gate GEMV over NKQ k-chunks: lane = slot column (s = lane + 32*(jbase+j)),
// warp covers batches bh*4..bh*4+3. acc[NJ][4] keeps registers lean.
template<int NKQ, int NJ>
__device__ __forceinline__ void gate_gemv(const ulonglong2* __restrict__ wp,
                                          const ulonglong2* __restrict__ hp,
                                          u64 (&acc)[NJ][4])
{
#pragma unroll
    for (int j = 0; j < NJ; j++)
#pragma unroll
        for (int b = 0; b < 4; b++) acc[j][b] = 0ull;
#pragma unroll
    for (int i = 0; i < NKQ; i++) {
        ulonglong2 h[4];
#pragma unroll
        for (int b = 0; b < 4; b++) h[b] = hp[b * HC + i];
#pragma unroll
        for (int j = 0; j < NJ; j++) {
            ulonglong2 w = wp[i * GP + 32 * j];
#pragma unroll
            for (int b = 0; b < 4; b++) {
                ffma2(acc[j][b], w.x, h[b].x);
                ffma2(acc[j][b], w.y, h[b].y);
            }
        }
    }
}

template<int NJ, bool ADDX>
__device__ __forceinline__ void store_partial(float* __restrict__ pb,
                                              const float* __restrict__ wiP,
                                              int bh, u64 (&acc)[NJ][4],
                                              const float* __restrict__ xrow)
{
    float wi[NJ];
    if (ADDX) {
#pragma unroll
        for (int j = 0; j < NJ; j++) wi[j] = wiP[32 * j];
    }
#pragma unroll
    for (int b = 0; b < 4; b++) {
        float xv = ADDX ? xrow[bh * 4 + b] : 0.0f;
#pragma unroll
        for (int j = 0; j < NJ; j++) {
            float2 p = unpk(acc[j][b]);
            float gv = p.x + p.y;
            if (ADDX) gv = fmaf(xv, wi[j], gv);
            pb[(bh * 4 + b) * GP + 32 * j] = gv;
        }
    }
}

// merged pointwise update (R8-proven): U2(t) + U1(t+1), independent chains.
// thread: b = job&7, u = job>>3, job < 408. Slots permuted (u,q) -> float4.
__device__ __forceinline__ void update_both(float* sm, int b, int u, bool act,
                                            bool doU1)
{
    if (!act) return;
    {
        const float4* p2 = (const float4*)(sm + OFF_PB2 + b * GP + 4 * u);
        float4 g = *(const float4*)(sm + OFF_B2 + 4 * u);
#pragma unroll
        for (int l = 0; l < 4; l++) {
            float4 p = p2[l * (LVL / 4)];
            g.x += p.x; g.y += p.y; g.z += p.z; g.w += p.w;
        }
        float c  = sm[OFF_C2 + b * 52 + u];
        float cn = sigf(g.y) * c + sigf(g.x) * tanhfast(g.z);
        float hn = sigf(g.w) * tanhfast(cn);
        sm[OFF_C2 + b * 52 + u] = cn;
        sm[OFF_HS + b * HROW + 52 + u] = hn;
    }
    if (doU1) {
        const float4* p1 = (const float4*)(sm + OFF_PB1 + b * GP + 4 * u);
        float4 g = *(const float4*)(sm + OFF_B1 + 4 * u);
#pragma unroll
        for (int l = 0; l < 2; l++) {
            float4 p = p1[l * (LVL / 4)];
            g.x += p.x; g.y += p.y; g.z += p.z; g.w += p.w;
        }
        float c  = sm[OFF_C1 + b * 52 + u];
        float cn = sigf(g.y) * c + sigf(g.x) * tanhfast(g.z);
        float hn = sigf(g.w) * tanhfast(cn);
        sm[OFF_C1 + b * 52 + u] = cn;
        sm[OFF_HS + b * HROW + u] = hn;
    }
}

__device__ __forceinline__ void update_l1(float* sm, int b, int u, bool act)
{
    if (!act) return;
    const float4* p1 = (const float4*)(sm + OFF_PB1 + b * GP + 4 * u);
    float4 g = *(const float4*)(sm + OFF_B1 + 4 * u);
#pragma unroll
    for (int l = 0; l < 2; l++) {
        float4 p = p1[l * (LVL / 4)];
        g.x += p.x; g.y += p.y; g.z += p.z; g.w += p.w;
    }
    float c  = sm[OFF_C1 + b * 52 + u];
    float cn = sigf(g.y) * c + sigf(g.x) * tanhfast(g.z);
    float hn = sigf(g.w) * tanhfast(cn);
    sm[OFF_C1 + b * 52 + u] = cn;
    sm[OFF_HS + b * HROW + u] = hn;
}

__device__ __forceinline__ void out_phase(const float* sm, int lane, int bid,
                                          int tcol, float* __restrict__ out)
{
    int ob = lane & 7, part = lane >> 3;            // 4 parts x 13 k
    float a = 0.0f;
#pragma unroll
    for (int kk = 0; kk < 13; kk++) {
        int k = part * 13 + kk;                     // k=51 -> zero pad
        a = fmaf(sm[OFF_HS + ob * HROW + 52 + k], sm[OFF_WL + k], a);
    }
    a += __shfl_xor_sync(0xffffffffu, a, 8);
    a += __shfl_xor_sync(0xffffffffu, a, 16);
    if (lane < 8)
        out[(bid * NB + ob) * TSTEPS + tcol] = a + sm[OFF_BL];
}

__global__ void __launch_bounds__(NTHR, 1)
lstm_kernel(const float* __restrict__ input,
            const float* __restrict__ Wih1, const float* __restrict__ Whh1,
            const float* __restrict__ bih1, const float* __restrict__ bhh1,
            const float* __restrict__ Wih2, const float* __restrict__ Whh2,
            const float* __restrict__ bih2, const float* __restrict__ bhh2,
            const float* __restrict__ Wlin, const float* __restrict__ blin,
            float* __restrict__ out)
{
    extern __shared__ float sm[];
    const int tid  = threadIdx.x;
    const int bid  = blockIdx.x;
    const int lane = tid & 31;
    const int wid  = tid >> 5;            // 0..23

    // ---- staging (slot s = 4u+q; original gate row og = q*51+u) ----
    for (int i = tid; i < NB * HROW; i += NTHR) sm[OFF_HS + i] = 0.0f;
    for (int i = tid; i < NB * 52 * 2; i += NTHR) sm[OFF_C1 + i] = 0.0f;
    for (int i = tid; i < TSTEPS * 8; i += NTHR) {
        int t = i >> 3, bb = i & 7;
        sm[OFF_XS + i] = input[t * BTOT + bid * NB + bb];
    }
    for (int i = tid; i < 13 * GP * 4; i += NTHR) {
        int c = i & 3, s = (i >> 2) % GP, kq = i / (GP * 4);
        int u = s >> 2, q = s & 3, k = 4 * kq + c;
        float v = 0.0f;
        if (u < H_ && k < H_) v = Whh1[(q * H_ + u) * H_ + k];
        sm[OFF_W1 + i] = v;
    }
    for (int i = tid; i < 26 * GP * 4; i += NTHR) {
        int c = i & 3, s = (i >> 2) % GP, kq = i / (GP * 4);
        int u = s >> 2, q = s & 3, k = 4 * kq + c;
        float v = 0.0f;
        if (u < H_) {
            if (k < H_)                  v = Wih2[(q * H_ + u) * H_ + k];
            else if (k >= 52 && k < 103) v = Whh2[(q * H_ + u) * H_ + (k - 52)];
        }
        sm[OFF_W2 + i] = v;
    }
    for (int i = tid; i < GP; i += NTHR) {
        int u = i >> 2, q = i & 3;
        float b1 = 0.0f, b2 = 0.0f, w1 = 0.0f;
        if (u < H_) {
            int og = q * H_ + u;
            b1 = bih1[og] + bhh1[og];
            b2 = bih2[og] + bhh2[og];
            w1 = Wih1[og];
        }
        sm[OFF_B1  + i] = b1;
        sm[OFF_B2  + i] = b2;
        sm[OFF_WI1 + i] = w1;
    }
    if (tid < 56) sm[OFF_WL + tid] = (tid < H_) ? Wlin[tid] : 0.0f;
    if (tid == 0) sm[OFF_BL] = blin[0];
    __syncthreads();

    // ---- warp roles: 3-way split (kh x bh x jh), 24 warps ----
    // wid 0..7  : L1: kh = wid>>2 (0..1), bh = (wid>>1)&1, jh = wid&1
    //             kq slices: kh0 [0,7) cnt7, kh1 [7,13) cnt6
    // wid 8..23 : L2: sub = wid-8, kh = sub>>2 (0..3), bh, jh likewise
    //             kq slices: [0,7),[7,14),[14,20),[20,26) cnt (7,7,6,6)
    const bool isL1 = (wid < 8);
    const int  sub  = isL1 ? wid : wid - 8;
    const int  kh   = sub >> 2;
    const int  bh   = (sub >> 1) & 1;
    const int  jh   = sub & 1;
    const int  jbase = jh ? 4 : 0;         // jh0: j 0..3 (NJ4), jh1: j 4..6 (NJ3)

    const int l1start[2] = {0, 7};
    const int l2start[4] = {0, 7, 14, 20};
    const int kstart = isL1 ? l1start[kh] : l2start[kh];

    const ulonglong2* __restrict__ wp =
        (const ulonglong2*)(sm + (isL1 ? OFF_W1 : OFF_W2))
        + kstart * GP + lane + 32 * jbase;
    const ulonglong2* __restrict__ hp =
        (const ulonglong2*)(sm + OFF_HS) + bh * 4 * HC + kstart;
    float* pb = sm + (isL1 ? OFF_PB1 : OFF_PB2) + kh * LVL + lane + 32 * jbase;
    const float* wiP = sm + OFF_WI1 + lane + 32 * jbase;

    const int ub = tid & 7;               // update batch (tid<408)
    const int uu = tid >> 3;               // update unit
    const bool uact = (tid < NB * H_);

    auto run_gemv = [&](const float* xrow) {
        if (isL1) {
            if (kh == 0) {
                if (jh == 0) { u64 a[4][4]; gate_gemv<7,4>(wp, hp, a); store_partial<4,true >(pb, wiP, bh, a, xrow); }
                else         { u64 a[3][4]; gate_gemv<7,3>(wp, hp, a); store_partial<3,true >(pb, wiP, bh, a, xrow); }
            } else {
                if (jh == 0) { u64 a[4][4]; gate_gemv<6,4>(wp, hp, a); store_partial<4,false>(pb, wiP, bh, a, xrow); }
                else         { u64 a[3][4]; gate_gemv<6,3>(wp, hp, a); store_partial<3,false>(pb, wiP, bh, a, xrow); }
            }
        } else {
            if (kh < 2) {
                if (jh == 0) { u64 a[4][4]; gate_gemv<7,4>(wp, hp, a); store_partial<4,false>(pb, wiP, bh, a, xrow); }
                else         { u64 a[3][4]; gate_gemv<7,3>(wp, hp, a); store_partial<3,false>(pb, wiP, bh, a, xrow); }
            } else {
                if (jh == 0) { u64 a[4][4]; gate_gemv<6,4>(wp, hp, a); store_partial<4,false>(pb, wiP, bh, a, xrow); }
                else         { u64 a[3][4]; gate_gemv<6,3>(wp, hp, a); store_partial<3,false>(pb, wiP, bh, a, xrow); }
            }
        }
    };

    // ---- prologue: G1(0), U1(0) ----
    if (isL1) run_gemv(sm + OFF_XS + 0 * 8);
    __syncthreads();
    update_l1(sm, ub, uu, uact);
    __syncthreads();

    // ---- pipelined recurrence ----
    for (int t = 0; t < TSTEPS; t++) {
        // phase A: G2(t) on L2 warps; G1(t+1) on L1 warps; out(t-1) on wid 7
        if (isL1) {
            if (t + 1 < TSTEPS) run_gemv(sm + OFF_XS + (t + 1) * 8);
            if (wid == 7 && t > 0) out_phase(sm, lane, bid, t - 1, out);
        } else {
            run_gemv(nullptr);
        }
        __syncthreads();

        // phase B: U2(t) + U1(t+1)
        update_both(sm, ub, uu, uact, t + 1 < TSTEPS);
        __syncthreads();
    }

    // ---- epilogue ----
    if (wid == 7) out_phase(sm, lane, bid, TSTEPS - 1, out);
}

extern "C" void kernel_launch(void* const* d_in, const int* in_sizes, int n_in,
                              void* d_out, int out_size)
{
    const float* input = (const float*)d_in[0];
    const float* Wih1  = (const float*)d_in[1];
    const float* Whh1  = (const float*)d_in[2];
    const float* bih1  = (const float*)d_in[3];
    const float* bhh1  = (const float*)d_in[4];
    const float* Wih2  = (const float*)d_in[5];
    const float* Whh2  = (const float*)d_in[6];
    const float* bih2  = (const float*)d_in[7];
    const float* bhh2  = (const float*)d_in[8];
    const float* Wlin  = (const float*)d_in[9];
    const float* blin  = (const float*)d_in[10];
    float* out = (float*)d_out;

    static bool attr_set = false;
    if (!attr_set) {
        cudaFuncSetAttribute(lstm_kernel,
                             cudaFuncAttributeMaxDynamicSharedMemorySize,
                             SMEM_BYTES);
        attr_set = true;
    }
    lstm_kernel<<<NBLK, NTHR, SMEM_BYTES>>>(input, Wih1, Whh1, bih1, bhh1,
                                            Wih2, Whh2, bih2, bhh2,
                                            Wlin, blin, out);
}

// round 12
// speedup vs baseline: 1.3917x; 1.3917x over previous
#include <cuda_runtime.h>

typedef unsigned long long u64;

#define H_      51
#define TSTEPS  512
#define BTOT    1024
#define NB      8                 // batch rows per block
#define NBLK    (BTOT / NB)       // 128 blocks
#define NTHR    512
#define GP_     224               // padded gate count (204 -> 224 = 7*32)
#define L1K4    13                // layer1 K: 52 -> 13 float4 chunks
#define L2K4    26                // layer2 K: 104 -> 26 float4 chunks
#define HROW    108               // h row: [h1(51)|pad|h2(51)|pad..]
#define HC      (HROW/4)          // 27 ulonglong2 per h row
#define PR1     228               // partial row stride per batch
#define PR2     (NB * PR1)        // per-level partial block (1824)
#define L1KH    3                 // layer1 k-levels
#define L2KH    6                 // layer2 k-levels (5,5,5,5,4,2 chunks)

// ---- shared memory layout (float offsets) ----
#define OFF_W1   0                          // [13][224][4]
#define OFF_W2   (OFF_W1 + L1K4*GP_*4)      // [26][224][4]
#define OFF_XS   (OFF_W2 + L2K4*GP_*4)      // [512][8]
#define OFF_HS   (OFF_XS + TSTEPS*NB)       // [8][108]
#define OFF_C1   (OFF_HS + NB*HROW)         // [8][52]
#define OFF_C2   (OFF_C1 + NB*52)           // [8][52]
#define OFF_PB   (OFF_C2 + NB*52)           // 9 levels x [8][228]: 3 L1 + 6 L2
#define OFF_PB2  (OFF_PB + L1KH*PR2)
#define OFF_B1   (OFF_PB + 9*PR2)           // 224
#define OFF_B2   (OFF_B1 + GP_)             // 224
#define OFF_WI1  (OFF_B2 + GP_)             // 224
#define OFF_WL   (OFF_WI1 + GP_)            // 52
#define OFF_BL   (OFF_WL + 52)              // 4
#define SMEM_FLOATS (OFF_BL + 4)
#define SMEM_BYTES  (SMEM_FLOATS * 4)       // ~231.5 KB (fits 227KB+... 232448B cap)

__device__ __forceinline__ void ffma2(u64 &d, u64 a, u64 b) {
    asm("fma.rn.f32x2 %0, %1, %2, %0;" : "+l"(d) : "l"(a), "l"(b));
}
__device__ __forceinline__ float2 unpk(u64 v) {
    float2 r;
    asm("mov.b64 {%0, %1}, %2;" : "=f"(r.x), "=f"(r.y) : "l"(v));
    return r;
}
__device__ __forceinline__ float sigf(float x) {
    return __fdividef(1.0f, 1.0f + __expf(-x));
}
__device__ __forceinline__ float tanhfast(float x) {
    return __fdividef(2.0f, 1.0f + __expf(-2.0f * x)) - 1.0f;
}

// gate GEMV over NKQ static k-chunks (R6-proven): lane = gate slot,
// warp covers batches bh*4..bh*4+3.
template<int NKQ>
__device__ __forceinline__ void gate_gemv(const ulonglong2* __restrict__ wp,
                                          const ulonglong2* __restrict__ hp,
                                          u64 (&acc)[7][4])
{
#pragma unroll
    for (int j = 0; j < 7; j++)
#pragma unroll
        for (int b = 0; b < 4; b++) acc[j][b] = 0ull;
#pragma unroll
    for (int i = 0; i < NKQ; i++) {
        ulonglong2 h[4];
#pragma unroll
        for (int b = 0; b < 4; b++) h[b] = hp[b * HC + i];
#pragma unroll
        for (int j = 0; j < 7; j++) {
            ulonglong2 w = wp[i * GP_ + 32 * j];
#pragma unroll
            for (int b = 0; b < 4; b++) {
                ffma2(acc[j][b], w.x, h[b].x);
                ffma2(acc[j][b], w.y, h[b].y);
            }
        }
    }
}

__device__ __forceinline__ void store_partial(float* __restrict__ pb,
                                              const float* __restrict__ sm,
                                              int lane, int bh,
                                              u64 (&acc)[7][4],
                                              bool addx, const float* xrow)
{
    float wi[7];
    if (addx) {
#pragma unroll
        for (int j = 0; j < 7; j++) wi[j] = sm[OFF_WI1 + lane + 32 * j];
    }
#pragma unroll
    for (int b = 0; b < 4; b++) {
        float xv = addx ? xrow[bh * 4 + b] : 0.0f;
#pragma unroll
        for (int j = 0; j < 7; j++) {
            float2 p = unpk(acc[j][b]);
            float gv = p.x + p.y;
            if (addx) gv = fmaf(xv, wi[j], gv);
            pb[(bh * 4 + b) * PR1 + 32 * j] = gv;
        }
    }
}

// pointwise cell update (R6-proven): 408 jobs (b, j); sums NLEV levels + bias
template<int NLEV>
__device__ __forceinline__ void update_phase(float* sm, int tid, int coff,
                                             int hoff, int boff, int pboff)
{
    if (tid < NB * H_) {
        int b = tid & 7, j = tid >> 3;              // j in 0..50
        float gi = sm[boff + j];
        float gf = sm[boff + 51 + j];
        float gg = sm[boff + 102 + j];
        float go = sm[boff + 153 + j];
        const float* pb = sm + pboff + b * PR1 + j;
#pragma unroll
        for (int l = 0; l < NLEV; l++) {
            const float* p = pb + l * PR2;
            gi += p[0];
            gf += p[51];
            gg += p[102];
            go += p[153];
        }
        float c  = sm[coff + b * 52 + j];
        float cn = sigf(gf) * c + sigf(gi) * tanhfast(gg);
        float hn = sigf(go) * tanhfast(cn);
        sm[coff + b * 52 + j] = cn;
        sm[OFF_HS + b * HROW + hoff + j] = hn;
    }
}

__device__ __forceinline__ void out_phase(const float* sm, int lane, int bid,
                                          int tcol, float* __restrict__ out)
{
    int ob = lane & 7, part = lane >> 3;            // 4 parts x 13 k
    float a = 0.0f;
#pragma unroll
    for (int kk = 0; kk < 13; kk++) {
        int k = part * 13 + kk;                     // k max 51 -> zero pad
        a = fmaf(sm[OFF_HS + ob * HROW + 52 + k], sm[OFF_WL + k], a);
    }
    a += __shfl_xor_sync(0xffffffffu, a, 8);
    a += __shfl_xor_sync(0xffffffffu, a, 16);
    if (lane < 8)
        out[(bid * NB + ob) * TSTEPS + tcol] = a + sm[OFF_BL];
}

__global__ void __launch_bounds__(NTHR, 1)
lstm_kernel(const float* __restrict__ input,
            const float* __restrict__ Wih1, const float* __restrict__ Whh1,
            const float* __restrict__ bih1, const float* __restrict__ bhh1,
            const float* __restrict__ Wih2, const float* __restrict__ Whh2,
            const float* __restrict__ bih2, const float* __restrict__ bhh2,
            const float* __restrict__ Wlin, const float* __restrict__ blin,
            float* __restrict__ out)
{
    extern __shared__ float sm[];
    const int tid  = threadIdx.x;
    const int bid  = blockIdx.x;
    const int lane = tid & 31;
    const int wid  = tid >> 5;            // 0..15
    const int role = wid >> 1;            // 0..7
    const int bh   = wid & 1;             // batch half

    // ---- staging ----
    for (int i = tid; i < NB * HROW; i += NTHR) sm[OFF_HS + i] = 0.0f;
    for (int i = tid; i < NB * 52 * 2; i += NTHR) sm[OFF_C1 + i] = 0.0f;

    for (int i = tid; i < TSTEPS * NB; i += NTHR) {
        int t = i >> 3, bb = i & 7;
        sm[OFF_XS + i] = input[t * BTOT + bid * NB + bb];
    }
    for (int i = tid; i < L1K4 * GP_ * 4; i += NTHR) {
        int c = i & 3, g = (i >> 2) % GP_, kq = i / (GP_ * 4);
        int k = 4 * kq + c;
        sm[OFF_W1 + i] = (g < 204 && k < H_) ? Whh1[g * H_ + k] : 0.0f;
    }
    for (int i = tid; i < L2K4 * GP_ * 4; i += NTHR) {
        int c = i & 3, g = (i >> 2) % GP_, kq = i / (GP_ * 4);
        int k = 4 * kq + c;
        float v = 0.0f;
        if (g < 204) {
            if (k < H_)                  v = Wih2[g * H_ + k];
            else if (k >= 52 && k < 103) v = Whh2[g * H_ + (k - 52)];
        }
        sm[OFF_W2 + i] = v;
    }
    for (int i = tid; i < GP_; i += NTHR) {
        sm[OFF_B1  + i] = (i < 204) ? bih1[i] + bhh1[i] : 0.0f;
        sm[OFF_B2  + i] = (i < 204) ? bih2[i] + bhh2[i] : 0.0f;
        sm[OFF_WI1 + i] = (i < 204) ? Wih1[i] : 0.0f;
    }
    if (tid < 52) sm[OFF_WL + tid] = (tid < H_) ? Wlin[tid] : 0.0f;
    if (tid == 0) sm[OFF_BL] = blin[0];
    __syncthreads();

    // ---- balanced warp roles (per bh): visits {5,5,5,5,5,5,5,4} ----
    // role0: L1 kq[0,5)  lvl0 +x      role1: L1 kq[5,10)  lvl1
    // role2: L1 kq[10,13) lvl2  AND  L2 kq[24,26) lvl5
    // role3: L2 [0,5) lvl0   role4: [5,10) lvl1   role5: [10,15) lvl2
    // role6: L2 [15,20) lvl3 role7: [20,24) lvl4 (+out duty on bh0)
    const bool hasL1 = (role <= 2);
    const bool hasL2 = (role >= 2);

    const int l1start[3] = {0, 5, 10};
    const int l2start[6] = {24, 0, 5, 10, 15, 20};   // indexed by role-2
    const int l2level[6] = {5, 0, 1, 2, 3, 4};

    int k1 = hasL1 ? l1start[role] : 0;
    int k2 = hasL2 ? l2start[role - 2] : 0;
    int lvl2 = hasL2 ? l2level[role - 2] : 0;

    const ulonglong2* __restrict__ wp1 =
        (const ulonglong2*)(sm + OFF_W1) + k1 * GP_ + lane;
    const ulonglong2* __restrict__ wp2 =
        (const ulonglong2*)(sm + OFF_W2) + k2 * GP_ + lane;
    const ulonglong2* __restrict__ hp1 =
        (const ulonglong2*)(sm + OFF_HS) + bh * 4 * HC + k1;
    const ulonglong2* __restrict__ hp2 =
        (const ulonglong2*)(sm + OFF_HS) + bh * 4 * HC + k2;
    float* pb1 = sm + OFF_PB + role * PR2 + lane;            // L1 lvl = role
    float* pb2 = sm + OFF_PB2 + lvl2 * PR2 + lane;

    u64 acc[7][4];

    auto do_l1 = [&](const float* xrow) {
        if (role == 0)      { gate_gemv<5>(wp1, hp1, acc); store_partial(pb1, sm, lane, bh, acc, true,  xrow); }
        else if (role == 1) { gate_gemv<5>(wp1, hp1, acc); store_partial(pb1, sm, lane, bh, acc, false, xrow); }
        else                { gate_gemv<3>(wp1, hp1, acc); store_partial(pb1, sm, lane, bh, acc, false, xrow); }
    };
    auto do_l2 = [&]() {
        if (role == 2)      { gate_gemv<2>(wp2, hp2, acc); }
        else if (role == 7) { gate_gemv<4>(wp2, hp2, acc); }
        else                { gate_gemv<5>(wp2, hp2, acc); }
        store_partial(pb2, sm, lane, bh, acc, false, nullptr);
    };

    // ---- prologue: G1(0), U1(0) ----
    if (hasL1) do_l1(sm + OFF_XS + 0 * NB);
    __syncthreads();
    update_phase<L1KH>(sm, tid, OFF_C1, 0, OFF_B1, OFF_PB);
    __syncthreads();

    // ---- pipelined recurrence ----
    for (int t = 0; t < TSTEPS; t++) {
        // phase A: G2(t) + G1(t+1) + out(t-1)
        if (hasL1 && t + 1 < TSTEPS) do_l1(sm + OFF_XS + (t + 1) * NB);
        if (hasL2) do_l2();
        if (wid == 14 && t > 0) out_phase(sm, lane, bid, t - 1, out);
        __syncthreads();

        // phase B: U2(t) then U1(t+1)
        update_phase<L2KH>(sm, tid, OFF_C2, 52, OFF_B2, OFF_PB2);
        if (t + 1 < TSTEPS)
            update_phase<L1KH>(sm, tid, OFF_C1, 0, OFF_B1, OFF_PB);
        __syncthreads();
    }

    // ---- epilogue: out(511) ----
    if (wid == 14) out_phase(sm, lane, bid, TSTEPS - 1, out);
}

extern "C" void kernel_launch(void* const* d_in, const int* in_sizes, int n_in,
                              void* d_out, int out_size)
{
    const float* input = (const float*)d_in[0];
    const float* Wih1  = (const float*)d_in[1];
    const float* Whh1  = (const float*)d_in[2];
    const float* bih1  = (const float*)d_in[3];
    const float* bhh1  = (const float*)d_in[4];
    const float* Wih2  = (const float*)d_in[5];
    const float* Whh2  = (const float*)d_in[6];
    const float* bih2  = (const float*)d_in[7];
    const float* bhh2  = (const float*)d_in[8];
    const float* Wlin  = (const float*)d_in[9];
    const float* blin  = (const float*)d_in[10];
    float* out = (float*)d_out;

    static bool attr_set = false;
    if (!attr_set) {
        cudaFuncSetAttribute(lstm_kernel,
                             cudaFuncAttributeMaxDynamicSharedMemorySize,
                             SMEM_BYTES);
        attr_set = true;
    }
    lstm_kernel<<<NBLK, NTHR, SMEM_BYTES>>>(input, Wih1, Whh1, bih1, bhh1,
                                            Wih2, Whh2, bih2, bhh2,
                                            Wlin, blin, out);
}